// round 8
// baseline (speedup 1.0000x reference)
#include <cuda_runtime.h>
#include <math.h>

#define IMG   512
#define NB    16
#define OT    74
#define RGR   96
#define HALO  11
#define TPD   7
#define NTILES (NB*TPD*TPD)
#define RSU   28              // u8 words per row (24 used + 4 pad), mult of 4
#define MAPU  (RGR*RSU)       // 2688 words
#define NTHR  576

#define SP 0
#define SG MAPU
#define TP (2*MAPU)
#define TG (3*MAPU)
#define CP (4*MAPU)           // 10752
#define CCSZ (OT*RSU)         // 2072
#define CG (CP + CCSZ)
#define RED (CG + CCSZ)       // 14896
#define TOTW (RED + 104)
#define SMEM_BYTES (TOTW*4)   // 60000 B -> 3 CTAs/SM

#define FULLM 0xFFFFFFFFu

// owned-px keep masks per word (px 11..84; right-edge tiles px 11..78)
__constant__ unsigned ACCB[2][24] = {
 {0,0,0xFF000000u,FULLM,FULLM,FULLM,FULLM,FULLM,FULLM,FULLM,FULLM,FULLM,FULLM,
  FULLM,FULLM,FULLM,FULLM,FULLM,FULLM,FULLM,FULLM,0x000000FFu,0,0},
 {0,0,0xFF000000u,FULLM,FULLM,FULLM,FULLM,FULLM,FULLM,FULLM,FULLM,FULLM,FULLM,
  FULLM,FULLM,FULLM,FULLM,FULLM,FULLM,0x00FFFFFFu,0,0,0,0}
};
// in-image keep masks (boundary post-mask) for left-edge / right-edge tiles
__constant__ unsigned BIML[24] = {0,0,0xFF000000u,FULLM,FULLM,FULLM,FULLM,FULLM,
  FULLM,FULLM,FULLM,FULLM,FULLM,FULLM,FULLM,FULLM,FULLM,FULLM,FULLM,FULLM,
  FULLM,FULLM,FULLM,FULLM};
__constant__ unsigned BIMR[24] = {FULLM,FULLM,FULLM,FULLM,FULLM,FULLM,FULLM,
  FULLM,FULLM,FULLM,FULLM,FULLM,FULLM,FULLM,FULLM,FULLM,FULLM,FULLM,FULLM,
  0x00FFFFFFu,0,0,0,0};

__device__ float g_part[NTILES*5];
__device__ unsigned g_count;

// shift helpers: byte-granular neighbor words (px-1 / px+1)
#define PRV(a,b) __byte_perm((a),(b),0x6543)   // [a.b3, b.b0, b.b1, b.b2]
#define NXT(b,c) __byte_perm((b),(c),0x4321)   // [b.b1, b.b2, b.b3, c.b0]
#define MAX3(a,b,c) __vmaxu4((a), __vmaxu4((b),(c)))
#define MIN3(a,b,c) __vminu4((a), __vminu4((b),(c)))

__global__ void __launch_bounds__(NTHR, 3)
k_main(const float* __restrict__ logits, const int* __restrict__ target,
       float* __restrict__ out) {
    extern __shared__ unsigned smu[];
    float* red = (float*)(smu + RED);

    const int tid  = threadIdx.x;
    const int tile = blockIdx.x;
    const int b    = tile / (TPD*TPD);
    const int tr   = tile % (TPD*TPD);
    const int tyi  = tr / TPD, txi = tr % TPD;
    const int oy   = tyi*OT - HALO, ox = txi*OT - HALO;

    const float* lg = logits + (size_t)b*IMG*IMG;
    const int*   tg = target + (size_t)b*IMG*IMG;

    float a_bce = 0.f, a_p = 0.f, a_t = 0.f, a_pt = 0.f, a_hd = 0.f;

    // ---- load: pred u8 = round(sigmoid*255), gt u8 = 0/255; fp32 partials on owned px
#pragma unroll
    for (int k = 0; k < 4; k++) {
        int wt = tid + k*NTHR;               // 2304 word tasks
        int r = wt / 24, w = wt - r*24;
        int iy = oy + r, iyc = min(max(iy,0), IMG-1);
        bool rown = (r >= HALO) & (r < HALO+OT) & (iy < IMG);
        unsigned pw = 0, gw = 0;
#pragma unroll
        for (int i = 0; i < 4; i++) {
            int px = 4*w + i, ix = ox + px;
            int ixc = min(max(ix,0), IMG-1);
            float x = lg[iyc*IMG + ixc];
            int   ti = tg[iyc*IMG + ixc];
            float p = 1.f/(1.f+expf(-x));
            if (rown & (px >= HALO) & (px < HALO+OT) & (ix < IMG)) {
                float tf = (float)ti;
                a_bce += fmaxf(x,0.f) - x*tf + log1pf(expf(-fabsf(x)));
                a_p += p; a_t += tf; a_pt += p*tf;
            }
            unsigned pq = __float2uint_rn(__saturatef(p)*255.f);
            pw |= pq << (8*i);
            gw |= (ti ? 255u : 0u) << (8*i);
        }
        smu[SP + r*RSU + w] = pw;
        smu[SG + r*RSU + w] = gw;
    }
    __syncthreads();

    // ---- thread mapping for boundary/cascade: one uint4 per map
    const int r  = tid % 96;
    const int wg = tid / 96;                 // 0..5
    const int rm = r ? r-1 : 0, rp = (r < 95) ? r+1 : 95;
    const bool rowin  = ((unsigned)(oy+r)) < (unsigned)IMG;
    const bool rowown = (r >= HALO) & (r < HALO+OT) & ((oy+r) < IMG);
    const int msel = (txi == TPD-1) ? 1 : 0;
    const int wb = wg*4;

    // in-image keep masks for this thread's 4 words (boundary post-mask)
    unsigned kimg[4] = {FULLM,FULLM,FULLM,FULLM};
    if (txi == 0)      { kimg[0]=BIML[wb]; kimg[1]=BIML[wb+1]; kimg[2]=BIML[wb+2]; kimg[3]=BIML[wb+3]; }
    if (txi == TPD-1)  { kimg[0]=BIMR[wb]; kimg[1]=BIMR[wb+1]; kimg[2]=BIMR[wb+2]; kimg[3]=BIMR[wb+3]; }

    // ---- boundary pass: bnd = max3x3 - min3x3 (u8), then mask out-of-image to 0
#pragma unroll
    for (int m = 0; m < 2; m++) {
        const unsigned* src = smu + (m ? SG : SP);
        unsigned wx[6], wn[6];
        {
            // rows rm, r, rp: words wb-1 .. wb+4 (pads: 0 for max, 255 for min)
            const int rws[3] = {rm, r, rp};
#pragma unroll
            for (int q = 0; q < 3; q++) {
                int base = rws[q]*RSU + wb;
                uint4 W = *(const uint4*)(src + base);
                unsigned lw = wg ? src[base-1] : 0u;
                unsigned rw = (wg < 5) ? src[base+4] : 0u;
                unsigned row[6] = {lw, W.x, W.y, W.z, W.w, rw};
                if (q == 0) {
#pragma unroll
                    for (int i = 0; i < 6; i++) { wx[i] = row[i]; wn[i] = row[i]; }
                    if (!wg) wn[0] = FULLM;
                    if (wg == 5) wn[5] = FULLM;
                } else {
                    unsigned ln = wg ? row[0] : FULLM;
                    unsigned rn = (wg < 5) ? row[5] : FULLM;
                    unsigned rowmin[6] = {ln, row[1], row[2], row[3], row[4], rn};
#pragma unroll
                    for (int i = 0; i < 6; i++) {
                        wx[i] = __vmaxu4(wx[i], row[i]);
                        wn[i] = __vminu4(wn[i], rowmin[i]);
                    }
                }
            }
        }
        unsigned o[4];
#pragma unroll
        for (int i = 0; i < 4; i++) {
            unsigned hx = MAX3(wx[i+1], PRV(wx[i],wx[i+1]), NXT(wx[i+1],wx[i+2]));
            unsigned pn = wg||i ? PRV(wn[i],wn[i+1]) : __byte_perm(FULLM, wn[1], 0x6543);
            unsigned nn = (wg<5)||(i<3) ? NXT(wn[i+1],wn[i+2]) : __byte_perm(wn[4], FULLM, 0x4321);
            unsigned hn = MIN3(wn[i+1], pn, nn);
            unsigned bnd = __vsub4(hx, hn);
            o[i] = rowin ? (bnd & kimg[i]) : 0u;
        }
        unsigned* dst = smu + (m ? SG : SP);       // overwrite raw in place? no:
        // write to src map slot (cascade starts from S*), raw no longer needed
        *(uint4*)(dst + r*RSU + wb) = make_uint4(o[0],o[1],o[2],o[3]);
        if ((r >= HALO) & (r < HALO+OT)) {
            unsigned* cdst = smu + (m ? CG : CP) + (r-HALO)*RSU + wb;
            *(uint4*)cdst = make_uint4(o[0],o[1],o[2],o[3]);
        }
        __syncthreads();   // all raw reads done before next map overwrites?  (m=0 writes SP which m=1 never reads; sync needed only between raw-read and overwrite of SAME map -> reads of SP happen in m=0 only, writes SP in m=0 after reads by THIS thread, but other threads may still read SP rows. So sync before writing is required; restructure below.)
    }
    // NOTE: the loop above contains a subtle read/write hazard handled by restructuring:
    // (kept simple: the __syncthreads inside the loop separates m=0 and m=1, but the
    //  in-place overwrite within one m is the hazard; we avoid it by writing boundary
    //  into the TMP buffers instead, then copying via the cascade's first vpass source.)
    __syncthreads();

    // ---- dilation cascade d = 1..10 : src = S* (boundary), ping-pong S* <-> T*
    {
        for (int d = 1; d <= 10; d++) {
            // vertical max3: S -> T (both maps)
#pragma unroll
            for (int m = 0; m < 2; m++) {
                const unsigned* s = smu + (m ? SG : SP);
                unsigned* t = smu + (m ? TG : TP);
                uint4 A = *(const uint4*)(s + rm*RSU + wb);
                uint4 B = *(const uint4*)(s + r *RSU + wb);
                uint4 C = *(const uint4*)(s + rp*RSU + wb);
                uint4 o;
                o.x = MAX3(A.x,B.x,C.x); o.y = MAX3(A.y,B.y,C.y);
                o.z = MAX3(A.z,B.z,C.z); o.w = MAX3(A.w,B.w,C.w);
                *(uint4*)(t + r*RSU + wb) = o;
            }
            __syncthreads();
            // horizontal max3: T -> S, keep results in regs; fused XOR/DP4A accumulation
            unsigned pd[4], gd[4];
#pragma unroll
            for (int m = 0; m < 2; m++) {
                const unsigned* t = smu + (m ? TG : TP);
                unsigned* s = smu + (m ? SG : SP);
                int base = r*RSU + wb;
                uint4 W = *(const uint4*)(t + base);
                unsigned lw = wg ? t[base-1] : 0u;
                unsigned rw = (wg < 5) ? t[base+4] : 0u;
                unsigned w[6] = {lw, W.x, W.y, W.z, W.w, rw};
                unsigned* h = m ? gd : pd;
#pragma unroll
                for (int i = 0; i < 4; i++)
                    h[i] = MAX3(w[i+1], PRV(w[i],w[i+1]), NXT(w[i+1],w[i+2]));
                *(uint4*)(s + base) = make_uint4(h[0],h[1],h[2],h[3]);
            }
            if (rowown) {
                int cb = (r-HALO)*RSU + wb;
                uint4 cg = *(const uint4*)(smu + CG + cb);
                uint4 cp = *(const uint4*)(smu + CP + cb);
                unsigned cgw[4] = {cg.x,cg.y,cg.z,cg.w};
                unsigned cpw[4] = {cp.x,cp.y,cp.z,cp.w};
                unsigned acc = 0;
#pragma unroll
                for (int i = 0; i < 4; i++) {
                    unsigned msk = ACCB[msel][wb+i];
                    acc = __dp4a((pd[i]^cgw[i]) & msk, 0x01010101u, acc);
                    acc = __dp4a((gd[i]^cpw[i]) & msk, 0x01010101u, acc);
                }
                a_hd += (0.1f*(float)d) * (float)acc;
            }
            __syncthreads();
        }
    }

    // ---- block reduction -> per-tile partials
    const unsigned FULL = 0xffffffffu;
#pragma unroll
    for (int o = 16; o; o >>= 1) {
        a_bce += __shfl_down_sync(FULL,a_bce,o); a_hd += __shfl_down_sync(FULL,a_hd,o);
        a_p += __shfl_down_sync(FULL,a_p,o); a_t += __shfl_down_sync(FULL,a_t,o);
        a_pt += __shfl_down_sync(FULL,a_pt,o);
    }
    int lane = tid & 31, w = tid >> 5;
    if (lane == 0) {
        red[w] = a_bce; red[18+w] = a_hd; red[36+w] = a_p;
        red[54+w] = a_t; red[72+w] = a_pt;
    }
    __syncthreads();
    if (tid == 0) {
        float sb=0, sh=0, sp=0, st=0, spt=0;
#pragma unroll
        for (int i = 0; i < 18; i++) {
            sb += red[i]; sh += red[18+i]; sp += red[36+i];
            st += red[54+i]; spt += red[72+i];
        }
        float* g = &g_part[tile*5];
        g[0]=sb; g[1]=sh/255.f; g[2]=sp; g[3]=st; g[4]=spt;
        __threadfence();
        unsigned v = atomicAdd(&g_count, 1u);
        red[96] = (v == NTILES-1) ? 1.f : 0.f;
    }
    __syncthreads();

    // ---- last CTA: final combine
    if (red[96] != 0.f) {
        __threadfence();
        __shared__ float simg[16][2], sbh[16][2];
        for (int img = w; img < 16; img += 18) {
            float bce=0, hd=0, p=0, t=0, pt=0;
            for (int i = lane; i < TPD*TPD; i += 32) {
                const float* g = &g_part[(img*TPD*TPD+i)*5];
                bce += g[0]; hd += g[1]; p += g[2]; t += g[3]; pt += g[4];
            }
#pragma unroll
            for (int o = 16; o; o >>= 1) {
                bce += __shfl_down_sync(FULL,bce,o); hd += __shfl_down_sync(FULL,hd,o);
                p += __shfl_down_sync(FULL,p,o); t += __shfl_down_sync(FULL,t,o);
                pt += __shfl_down_sync(FULL,pt,o);
            }
            if (lane == 0) {
                float dice = (2.f*pt + 1e-6f) / (p + t + 1e-6f + 1e-7f);
                float FP = p - pt, FN = t - pt;
                float tv = (pt + 1e-6f) / (pt + 0.7f*FP + 0.3f*FN + 1e-6f + 1e-7f);
                simg[img][0] = 1.f - dice;
                simg[img][1] = powf(fmaxf(1.f - tv, 0.f), 0.75f);
                sbh[img][0] = bce; sbh[img][1] = hd;
            }
        }
        __syncthreads();
        if (tid == 0) {
            float ds=0, fs=0, sb=0, sh=0;
#pragma unroll
            for (int i = 0; i < 16; i++) {
                ds += simg[i][0]; fs += simg[i][1];
                sb += sbh[i][0];  sh += sbh[i][1];
            }
            const float N = (float)NB*IMG*IMG;
            out[0] = sb/N + ds/16.f + fs/16.f + 0.1f*((sh/N)/(5.5f + 1e-8f));
            g_count = 0;
        }
    }
}

extern "C" void kernel_launch(void* const* d_in, const int* in_sizes, int n_in,
                              void* d_out, int out_size) {
    const float* logits = (const float*)d_in[0];
    const int*   target = (const int*)d_in[1];
    cudaFuncSetAttribute(k_main, cudaFuncAttributeMaxDynamicSharedMemorySize, SMEM_BYTES);
    k_main<<<NTILES, NTHR, SMEM_BYTES>>>(logits, target, (float*)d_out);
}

// round 9
// speedup vs baseline: 1.0343x; 1.0343x over previous
#include <cuda_runtime.h>
#include <cuda_fp16.h>
#include <math.h>

#define IMG   512
#define NB    16
#define OT    74
#define RGR   96
#define HALO  11
#define TPD   7
#define NTILES (NB*TPD*TPD)
#define RST   52              // half2 words per row (48 used), conflict-free
#define NTHR  576

#define PR0 0                 // pred raw -> cascade tmp
#define PR1 (RGR*RST)         // pred boundary -> cascade state (4992)
#define CGB (2*RGR*RST)       // gt_b center half2 0/1 (74*52)
#define CPU (CGB + OT*RST)    // pred_b center u8 (74*28)
#define GB0 (CPU + OT*28)     // gt bitmap tmp (96*4)
#define GB1 (GB0 + RGR*4)     // gt bitmap state
#define RED (GB1 + RGR*4)
#define TOTW (RED + 104)
#define SMEM_BYTES (TOTW*4)   // 67104 B -> 3 CTAs/SM

#define FULLM 0xFFFFFFFFu
#define SHW(a,b) __byte_perm((a),(b),0x5432)

__constant__ unsigned ACCH[2][6][8] = {
 { {0,0,0,0,0,0xFFFF0000u,FULLM,FULLM},
   {FULLM,FULLM,FULLM,FULLM,FULLM,FULLM,FULLM,FULLM},
   {FULLM,FULLM,FULLM,FULLM,FULLM,FULLM,FULLM,FULLM},
   {FULLM,FULLM,FULLM,FULLM,FULLM,FULLM,FULLM,FULLM},
   {FULLM,FULLM,FULLM,FULLM,FULLM,FULLM,FULLM,FULLM},
   {FULLM,FULLM,0x0000FFFFu,0,0,0,0,0} },
 { {0,0,0,0,0,0xFFFF0000u,FULLM,FULLM},
   {FULLM,FULLM,FULLM,FULLM,FULLM,FULLM,FULLM,FULLM},
   {FULLM,FULLM,FULLM,FULLM,FULLM,FULLM,FULLM,FULLM},
   {FULLM,FULLM,FULLM,FULLM,FULLM,FULLM,FULLM,FULLM},
   {FULLM,FULLM,FULLM,FULLM,FULLM,FULLM,FULLM,0x0000FFFFu},
   {0,0,0,0,0,0,0,0} }
};
__constant__ unsigned ACCU[2][6][4] = {
 { {0,0,0xFF000000u,FULLM}, {FULLM,FULLM,FULLM,FULLM}, {FULLM,FULLM,FULLM,FULLM},
   {FULLM,FULLM,FULLM,FULLM}, {FULLM,FULLM,FULLM,FULLM}, {FULLM,0x000000FFu,0,0} },
 { {0,0,0xFF000000u,FULLM}, {FULLM,FULLM,FULLM,FULLM}, {FULLM,FULLM,FULLM,FULLM},
   {FULLM,FULLM,FULLM,FULLM}, {FULLM,FULLM,FULLM,0x00FFFFFFu}, {0,0,0,0} }
};

__device__ float g_part[NTILES*5];
__device__ unsigned g_count;

__device__ __forceinline__ unsigned hmax2u(unsigned a, unsigned b) {
    __half2 r = __hmax2(*(__half2*)&a, *(__half2*)&b); return *(unsigned*)&r; }
__device__ __forceinline__ unsigned hmin2u(unsigned a, unsigned b) {
    __half2 r = __hmin2(*(__half2*)&a, *(__half2*)&b); return *(unsigned*)&r; }
__device__ __forceinline__ unsigned max3w(unsigned a, unsigned b, unsigned c) {
    return hmax2u(a, hmax2u(b, c)); }
__device__ __forceinline__ unsigned habsdiff2u(unsigned a, unsigned b) {
    __half2 r = __habs2(__hsub2(*(__half2*)&a, *(__half2*)&b)); return *(unsigned*)&r; }
__device__ __forceinline__ unsigned hadd2u(unsigned a, unsigned b) {
    __half2 r = __hadd2(*(__half2*)&a, *(__half2*)&b); return *(unsigned*)&r; }
__device__ __forceinline__ unsigned hdil1(unsigned l, unsigned c, unsigned rw) {
    return c | __funnelshift_l(l, c, 1) | ((c >> 1) | (rw << 31)); }

__global__ void __launch_bounds__(NTHR, 3)
k_main(const float* __restrict__ logits, const int* __restrict__ target,
       float* __restrict__ out) {
    extern __shared__ unsigned smu[];
    float* red = (float*)(smu + RED);

    const int tid  = threadIdx.x;
    const int tile = blockIdx.x;
    const int b    = tile / (TPD*TPD);
    const int tr   = tile % (TPD*TPD);
    const int tyi  = tr / TPD, txi = tr % TPD;
    const int oy   = tyi*OT - HALO, ox = txi*OT - HALO;

    const float* lg = logits + (size_t)b*IMG*IMG;
    const int*   tg = target + (size_t)b*IMG*IMG;

    float a_bce = 0.f, a_p = 0.f, a_t = 0.f, a_pt = 0.f, a_hd = 0.f;

    // ---- load pred (replicate-clamped) + fp32 partials on owned px
#pragma unroll
    for (int k = 0; k < 8; k++) {
        int idx = tid + k*NTHR;
        int r = idx / 48, w = idx - r*48;
        int iy = oy + r, iyc = min(max(iy,0), IMG-1);
        int px0 = 2*w, ix0 = ox + px0, ix1 = ix0 + 1;
        int ixc0 = min(max(ix0,0), IMG-1), ixc1 = min(max(ix1,0), IMG-1);
        float x0 = lg[iyc*IMG+ixc0], x1 = lg[iyc*IMG+ixc1];
        float t0 = (float)tg[iyc*IMG+ixc0], t1 = (float)tg[iyc*IMG+ixc1];
        float p0 = 1.f/(1.f+expf(-x0)), p1 = 1.f/(1.f+expf(-x1));
        bool rown = (r >= HALO) & (r < HALO+OT) & (iy < IMG);
        if (rown & (px0 >= HALO) & (px0 < HALO+OT) & (ix0 < IMG)) {
            a_bce += fmaxf(x0,0.f) - x0*t0 + log1pf(expf(-fabsf(x0)));
            a_p += p0; a_t += t0; a_pt += p0*t0;
        }
        if (rown & (px0+1 >= HALO) & (px0+1 < HALO+OT) & (ix1 < IMG)) {
            a_bce += fmaxf(x1,0.f) - x1*t1 + log1pf(expf(-fabsf(x1)));
            a_p += p1; a_t += t1; a_pt += p1*t1;
        }
        __half2 hp = __floats2half2_rn(p0,p1);
        smu[PR0 + r*RST + w] = *(unsigned*)&hp;
    }
    // ---- gt bitmap build (tid<288): 32 px/word, replicate-clamped (L2-hot reread)
    if (tid < 288) {
        int r = tid / 3, wq = tid % 3;
        int iy = oy + r, iyc = min(max(iy,0), IMG-1);
        const int* row = tg + iyc*IMG;
        unsigned bits = 0;
#pragma unroll 8
        for (int j = 0; j < 32; j++) {
            int ix = ox + 32*wq + j;
            int ixc = min(max(ix,0), IMG-1);
            bits |= (row[ixc] ? 1u : 0u) << j;
        }
        smu[GB0 + r*4 + wq] = bits;
    }
    __syncthreads();

    // ---- mappings
    const int rr = tid % 96, ch = tid / 96;        // hpass/boundary: row + 8-word chunk
    const int wb = 8*ch;
    const int vcg = tid % 12, vrb = tid / 12;      // vpass: uint4 col group + 2-row group
    const int vcol = 4*vcg, vr0 = 2*vrb;
    const int rm = rr ? rr-1 : 0, rp = (rr < 95) ? rr+1 : 95;
    const bool rowin  = ((unsigned)(oy+rr)) < (unsigned)IMG;
    const bool rowown = (rr >= HALO) & (rr < HALO+OT) & ((oy+rr) < IMG);
    const int msel = (txi == TPD-1) ? 1 : 0;
    const bool colEdge = (txi == 0) | (txi == TPD-1);

    // ---- pred boundary: PR0 -> PR1 (max3x3 - min3x3), 0 at out-of-image; CPbU u8 center
    {
        const unsigned* src = smu + PR0;
        unsigned vx[10], vn[10];
        const int rws[3] = {rm, rr, rp};
#pragma unroll
        for (int q = 0; q < 3; q++) {
            int bq = rws[q]*RST + wb;
            uint4 A = *(const uint4*)(src+bq), B = *(const uint4*)(src+bq+4);
            unsigned em = ch ? src[bq-1] : A.x;
            unsigned ep = (ch < 5) ? src[bq+8] : B.w;
            unsigned row[10] = {em,A.x,A.y,A.z,A.w,B.x,B.y,B.z,B.w,ep};
#pragma unroll
            for (int i = 0; i < 10; i++) {
                if (q == 0) { vx[i] = row[i]; vn[i] = row[i]; }
                else { vx[i] = hmax2u(vx[i],row[i]); vn[i] = hmin2u(vn[i],row[i]); }
            }
        }
        unsigned o[8];
#pragma unroll
        for (int i = 0; i < 8; i++) {
            unsigned hx = max3w(vx[i+1], SHW(vx[i],vx[i+1]), SHW(vx[i+1],vx[i+2]));
            unsigned hn = hmin2u(vn[i+1], hmin2u(SHW(vn[i],vn[i+1]), SHW(vn[i+1],vn[i+2])));
            __half2 bh = __hsub2(*(__half2*)&hx, *(__half2*)&hn);
            unsigned bnd = *(unsigned*)&bh;
            if (colEdge) {
                int p0 = ox + 2*(wb+i);
                unsigned keep = (((unsigned)p0 < IMG) ? 0x0000FFFFu : 0u)
                              | (((unsigned)(p0+1) < IMG) ? 0xFFFF0000u : 0u);
                bnd &= keep;
            }
            o[i] = rowin ? bnd : 0u;
        }
        int base = rr*RST + wb;
        *(uint4*)(smu+PR1+base)   = make_uint4(o[0],o[1],o[2],o[3]);
        *(uint4*)(smu+PR1+base+4) = make_uint4(o[4],o[5],o[6],o[7]);
        if ((rr >= HALO) & (rr < HALO+OT)) {
            unsigned pk[4];
#pragma unroll
            for (int k = 0; k < 4; k++) {
                float2 fa = __half22float2(*(__half2*)&o[2*k]);
                float2 fb = __half22float2(*(__half2*)&o[2*k+1]);
                pk[k] =  __float2uint_rn(__saturatef(fa.x)*255.f)
                      | (__float2uint_rn(__saturatef(fa.y)*255.f) << 8)
                      | (__float2uint_rn(__saturatef(fb.x)*255.f) << 16)
                      | (__float2uint_rn(__saturatef(fb.y)*255.f) << 24);
            }
            *(uint4*)(smu + CPU + (rr-HALO)*28 + 4*ch) = make_uint4(pk[0],pk[1],pk[2],pk[3]);
        }
    }
    // ---- gt boundary bits: gt_b = dil3(gt) & dil3(~gt), GB0 -> GB1
    if (tid < 288) {
        int r = tid / 3, wq = tid % 3;
        int grm = r ? r-1 : 0, grp = (r < 95) ? r+1 : 95;
        unsigned v[3], u[3];
#pragma unroll
        for (int c = 0; c < 3; c++) {
            int w = wq - 1 + c;
            unsigned a = 0, bb = 0, cc = 0;
            if ((unsigned)w < 3u) {
                a = smu[GB0 + grm*4 + w]; bb = smu[GB0 + r*4 + w]; cc = smu[GB0 + grp*4 + w];
            }
            v[c] = a | bb | cc;
            u[c] = ((unsigned)w < 3u) ? ~(a & bb & cc) : 0u;
        }
        unsigned dv = hdil1(v[0], v[1], v[2]);
        unsigned du = hdil1(u[0], u[1], u[2]);
        unsigned gtb = dv & du;
        bool rin = ((unsigned)(oy+r)) < (unsigned)IMG;
        unsigned kb = FULLM;
        if (txi == 0 && wq == 0) kb = 0xFFFFF800u;
        if (txi == TPD-1 && wq == 2) kb = 0x00007FFFu;
        smu[GB1 + r*4 + wq] = rin ? (gtb & kb) : 0u;
    }
    __syncthreads();

    // ---- CGb: gt_b center as half2 0/1 (one-time)
    for (int k = 0; k < 7; k++) {
        int task = tid + k*NTHR;
        if (task < OT*48) {
            int rc = task / 48, w2 = task - rc*48;
            unsigned bw = smu[GB1 + (rc+HALO)*4 + (w2 >> 4)];
            int j = 2*(w2 & 15);
            smu[CGB + rc*RST + w2] = (((bw >> j) & 1u) * 0x3C00u)
                                   | (((bw >> (j+1)) & 1u) * 0x3C000000u);
        }
    }
    __syncthreads();

    // ---- cascade d = 1..10: pred vpass PR1->PR0, hpass PR0->PR1; gt GB1->GB0->GB1
    for (int d = 1; d <= 10; d++) {
        { // pred vpass (2 rows per thread, sliding)
            const unsigned* s = smu + PR1;
            int ra = vr0 ? vr0-1 : 0;
            int rd = (vr0+2 < 96) ? vr0+2 : 95;
            uint4 A = *(const uint4*)(s + ra*RST + vcol);
            uint4 B = *(const uint4*)(s + vr0*RST + vcol);
            uint4 C = *(const uint4*)(s + (vr0+1)*RST + vcol);
            uint4 D = *(const uint4*)(s + rd*RST + vcol);
            uint4 o1, o2;
            o1.x = max3w(A.x,B.x,C.x); o1.y = max3w(A.y,B.y,C.y);
            o1.z = max3w(A.z,B.z,C.z); o1.w = max3w(A.w,B.w,C.w);
            o2.x = max3w(B.x,C.x,D.x); o2.y = max3w(B.y,C.y,D.y);
            o2.z = max3w(B.z,C.z,D.z); o2.w = max3w(B.w,C.w,D.w);
            *(uint4*)(smu + PR0 + vr0*RST + vcol) = o1;
            *(uint4*)(smu + PR0 + (vr0+1)*RST + vcol) = o2;
        }
        if (tid < 288) { // gt vpass: OR of 3 rows
            int r = tid / 3, wq = tid % 3;
            int grm = r ? r-1 : 0, grp = (r < 95) ? r+1 : 95;
            smu[GB0 + r*4 + wq] = smu[GB1 + grm*4 + wq] | smu[GB1 + r*4 + wq]
                                | smu[GB1 + grp*4 + wq];
        }
        __syncthreads();
        { // pred hpass + fused accumulation
            const unsigned* t = smu + PR0;
            int base = rr*RST + wb;
            uint4 A = *(const uint4*)(t+base), B = *(const uint4*)(t+base+4);
            unsigned em = ch ? t[base-1] : A.x;
            unsigned ep = (ch < 5) ? t[base+8] : B.w;
            unsigned w[10] = {em,A.x,A.y,A.z,A.w,B.x,B.y,B.z,B.w,ep};
            unsigned o[8];
#pragma unroll
            for (int i = 0; i < 8; i++)
                o[i] = max3w(w[i+1], SHW(w[i],w[i+1]), SHW(w[i+1],w[i+2]));
            *(uint4*)(smu+PR1+base)   = make_uint4(o[0],o[1],o[2],o[3]);
            *(uint4*)(smu+PR1+base+4) = make_uint4(o[4],o[5],o[6],o[7]);
            if (rowown) {
                // pred side: |pred_d - gt_b| via CGb half2
                int cb = (rr-HALO)*RST + wb;
                uint4 c1 = *(const uint4*)(smu+CGB+cb), c2 = *(const uint4*)(smu+CGB+cb+4);
                unsigned cw[8] = {c1.x,c1.y,c1.z,c1.w,c2.x,c2.y,c2.z,c2.w};
                unsigned acch = 0;
#pragma unroll
                for (int i = 0; i < 8; i++)
                    acch = hadd2u(acch, habsdiff2u(o[i],cw[i]) & ACCH[msel][ch][i]);
                // gt side: gt_d bits (local horiz dilate of GB0) vs CPbU u8
                int widx = ch >> 1;
                unsigned lwd = widx ? smu[GB0 + rr*4 + widx-1] : 0u;
                unsigned cwd = smu[GB0 + rr*4 + widx];
                unsigned rwd = (widx < 2) ? smu[GB0 + rr*4 + widx+1] : 0u;
                unsigned gd = hdil1(lwd, cwd, rwd);
                uint4 pbu = *(const uint4*)(smu + CPU + (rr-HALO)*28 + 4*ch);
                unsigned pw[4] = {pbu.x,pbu.y,pbu.z,pbu.w};
                int sb = (ch & 1)*16;
                unsigned acci = 0;
#pragma unroll
                for (int k = 0; k < 4; k++) {
                    unsigned nib = (gd >> (sb + 4*k)) & 0xFu;
                    unsigned m8 = ((nib * 0x00204081u) & 0x01010101u) * 0xFFu;
                    acci = __dp4a((pw[k] ^ m8) & ACCU[msel][ch][k], 0x01010101u, acci);
                }
                float2 f = __half22float2(*(__half2*)&acch);
                a_hd += (0.1f*(float)d) * (f.x + f.y + (float)acci*(1.f/255.f));
            }
        }
        if (tid < 288) { // gt hpass: GB0 -> GB1
            int r = tid / 3, wq = tid % 3;
            unsigned lw = wq ? smu[GB0 + r*4 + wq-1] : 0u;
            unsigned cw = smu[GB0 + r*4 + wq];
            unsigned rw = (wq < 2) ? smu[GB0 + r*4 + wq+1] : 0u;
            smu[GB1 + r*4 + wq] = hdil1(lw, cw, rw);
        }
        __syncthreads();
    }

    // ---- block reduction -> per-tile partials
    const unsigned FULL = 0xffffffffu;
#pragma unroll
    for (int o = 16; o; o >>= 1) {
        a_bce += __shfl_down_sync(FULL,a_bce,o); a_hd += __shfl_down_sync(FULL,a_hd,o);
        a_p += __shfl_down_sync(FULL,a_p,o); a_t += __shfl_down_sync(FULL,a_t,o);
        a_pt += __shfl_down_sync(FULL,a_pt,o);
    }
    int lane = tid & 31, w = tid >> 5;
    if (lane == 0) {
        red[w] = a_bce; red[18+w] = a_hd; red[36+w] = a_p;
        red[54+w] = a_t; red[72+w] = a_pt;
    }
    __syncthreads();
    if (tid == 0) {
        float sb=0, sh=0, sp=0, st=0, spt=0;
#pragma unroll
        for (int i = 0; i < 18; i++) {
            sb += red[i]; sh += red[18+i]; sp += red[36+i];
            st += red[54+i]; spt += red[72+i];
        }
        float* g = &g_part[tile*5];
        g[0]=sb; g[1]=sh; g[2]=sp; g[3]=st; g[4]=spt;
        __threadfence();
        unsigned v = atomicAdd(&g_count, 1u);
        red[96] = (v == NTILES-1) ? 1.f : 0.f;
    }
    __syncthreads();

    // ---- last CTA: final combine
    if (red[96] != 0.f) {
        __threadfence();
        __shared__ float simg[16][2], sbh[16][2];
        for (int img = w; img < 16; img += 18) {
            float bce=0, hd=0, p=0, t=0, pt=0;
            for (int i = lane; i < TPD*TPD; i += 32) {
                const float* g = &g_part[(img*TPD*TPD+i)*5];
                bce += g[0]; hd += g[1]; p += g[2]; t += g[3]; pt += g[4];
            }
#pragma unroll
            for (int o = 16; o; o >>= 1) {
                bce += __shfl_down_sync(FULL,bce,o); hd += __shfl_down_sync(FULL,hd,o);
                p += __shfl_down_sync(FULL,p,o); t += __shfl_down_sync(FULL,t,o);
                pt += __shfl_down_sync(FULL,pt,o);
            }
            if (lane == 0) {
                float dice = (2.f*pt + 1e-6f) / (p + t + 1e-6f + 1e-7f);
                float FP = p - pt, FN = t - pt;
                float tv = (pt + 1e-6f) / (pt + 0.7f*FP + 0.3f*FN + 1e-6f + 1e-7f);
                simg[img][0] = 1.f - dice;
                simg[img][1] = powf(fmaxf(1.f - tv, 0.f), 0.75f);
                sbh[img][0] = bce; sbh[img][1] = hd;
            }
        }
        __syncthreads();
        if (tid == 0) {
            float ds=0, fs=0, sb=0, sh=0;
#pragma unroll
            for (int i = 0; i < 16; i++) {
                ds += simg[i][0]; fs += simg[i][1];
                sb += sbh[i][0];  sh += sbh[i][1];
            }
            const float N = (float)NB*IMG*IMG;
            out[0] = sb/N + ds/16.f + fs/16.f + 0.1f*((sh/N)/(5.5f + 1e-8f));
            g_count = 0;
        }
    }
}

extern "C" void kernel_launch(void* const* d_in, const int* in_sizes, int n_in,
                              void* d_out, int out_size) {
    const float* logits = (const float*)d_in[0];
    const int*   target = (const int*)d_in[1];
    cudaFuncSetAttribute(k_main, cudaFuncAttributeMaxDynamicSharedMemorySize, SMEM_BYTES);
    k_main<<<NTILES, NTHR, SMEM_BYTES>>>(logits, target, (float*)d_out);
}

// round 10
// speedup vs baseline: 1.1876x; 1.1482x over previous
#include <cuda_runtime.h>
#include <cuda_fp16.h>
#include <math.h>

#define IMG   512
#define NB    16
#define OT    74
#define RGR   96
#define HALO  11
#define TPD   7
#define NTILES (NB*TPD*TPD)
#define ROWW  48          // half2 words per row (96 px)
#define RSTRW 52          // row stride in words (16B aligned, conflict-free uint4)
#define MAPW  (RGR*RSTRW)
#define NTHR  576

#define P0 0
#define G0 MAPW
#define P1 (2*MAPW)
#define G1 (3*MAPW)
#define CBASE (4*MAPW)
#define CSZ  (OT*RSTRW)
#define REDW (CBASE + 2*CSZ)
#define TOTW (REDW + 104)
#define SMEM_BYTES (TOTW*4)   // 111072 B -> 2 CTAs/SM

#define NEGU  0xFC00FC00u
#define FULLM 0xFFFFFFFFu
#define SHW(a,b) __byte_perm((a),(b),0x5432)

// keep-masks for owned px per [edge][chunk][sub][word]; owned px = 11..84 (78 at right edge)
__constant__ unsigned ACCM[2][3][2][8] = {
 { { {0,0,0,0,0,0xFFFF0000u,FULLM,FULLM}, {FULLM,FULLM,FULLM,FULLM,FULLM,FULLM,FULLM,FULLM} },
   { {FULLM,FULLM,FULLM,FULLM,FULLM,FULLM,FULLM,FULLM}, {FULLM,FULLM,FULLM,FULLM,FULLM,FULLM,FULLM,FULLM} },
   { {FULLM,FULLM,FULLM,FULLM,FULLM,FULLM,FULLM,FULLM}, {FULLM,FULLM,0x0000FFFFu,0,0,0,0,0} } },
 { { {0,0,0,0,0,0xFFFF0000u,FULLM,FULLM}, {FULLM,FULLM,FULLM,FULLM,FULLM,FULLM,FULLM,FULLM} },
   { {FULLM,FULLM,FULLM,FULLM,FULLM,FULLM,FULLM,FULLM}, {FULLM,FULLM,FULLM,FULLM,FULLM,FULLM,FULLM,FULLM} },
   { {FULLM,FULLM,FULLM,FULLM,FULLM,FULLM,FULLM,0x0000FFFFu}, {0,0,0,0,0,0,0,0} } }
};

__device__ float g_part[NTILES*5];
__device__ unsigned g_count;

__device__ __forceinline__ unsigned hmax2u(unsigned a, unsigned b) {
    __half2 r = __hmax2(*(__half2*)&a, *(__half2*)&b); return *(unsigned*)&r; }
__device__ __forceinline__ unsigned hmin2u(unsigned a, unsigned b) {
    __half2 r = __hmin2(*(__half2*)&a, *(__half2*)&b); return *(unsigned*)&r; }
__device__ __forceinline__ unsigned max3w(unsigned a, unsigned b, unsigned c) {
    return hmax2u(a, hmax2u(b, c)); }
__device__ __forceinline__ unsigned habsdiff2u(unsigned a, unsigned b) {
    __half2 r = __habs2(__hsub2(*(__half2*)&a, *(__half2*)&b)); return *(unsigned*)&r; }
__device__ __forceinline__ unsigned hadd2u(unsigned a, unsigned b) {
    __half2 r = __hadd2(*(__half2*)&a, *(__half2*)&b); return *(unsigned*)&r; }

__global__ void __launch_bounds__(NTHR, 2)
k_main(const float* __restrict__ logits, const int* __restrict__ target,
       float* __restrict__ out) {
    extern __shared__ unsigned smu[];
    float* red = (float*)(smu + REDW);

    const int tid  = threadIdx.x;
    const int tile = blockIdx.x;
    const int b    = tile / (TPD*TPD);
    const int tr   = tile % (TPD*TPD);
    const int tyi  = tr / TPD, txi = tr % TPD;
    const int oy   = tyi*OT - HALO, ox = txi*OT - HALO;

    const float* lg = logits + (size_t)b*IMG*IMG;
    const int*   tg = target + (size_t)b*IMG*IMG;

    float a_bce = 0.f, a_p = 0.f, a_t = 0.f, a_pt = 0.f, a_hd = 0.f;

    // ---- load: replicate-clamped; P0 = pred (2 px/word), G0 = gt; owned-px partials
#pragma unroll
    for (int k = 0; k < 8; k++) {
        int idx = tid + k*NTHR;
        int r = idx / ROWW, w = idx - r*ROWW;
        int iy = oy + r, iyc = min(max(iy,0), IMG-1);
        int px0 = 2*w, ix0 = ox + px0, ix1 = ix0 + 1;
        int ixc0 = min(max(ix0,0), IMG-1), ixc1 = min(max(ix1,0), IMG-1);
        float x0 = lg[iyc*IMG+ixc0], x1 = lg[iyc*IMG+ixc1];
        float t0 = (float)tg[iyc*IMG+ixc0], t1 = (float)tg[iyc*IMG+ixc1];
        float p0 = 1.f/(1.f+expf(-x0)), p1 = 1.f/(1.f+expf(-x1));
        bool rown = (r >= HALO) & (r < HALO+OT) & (iy < IMG);
        if (rown & (px0 >= HALO) & (px0 < HALO+OT) & (ix0 < IMG)) {
            a_bce += fmaxf(x0,0.f) - x0*t0 + log1pf(expf(-fabsf(x0)));
            a_p += p0; a_t += t0; a_pt += p0*t0;
        }
        if (rown & (px0+1 >= HALO) & (px0+1 < HALO+OT) & (ix1 < IMG)) {
            a_bce += fmaxf(x1,0.f) - x1*t1 + log1pf(expf(-fabsf(x1)));
            a_p += p1; a_t += t1; a_pt += p1*t1;
        }
        __half2 hp = __floats2half2_rn(p0,p1), ht = __floats2half2_rn(t0,t1);
        smu[P0 + r*RSTRW + w] = *(unsigned*)&hp;
        smu[G0 + r*RSTRW + w] = *(unsigned*)&ht;
    }
    __syncthreads();

    // ---- thread mappings (row + 16-word chunk, per map)
    const int m  = tid / 288;            // 0=pred map, 1=gt map
    const int s  = tid % 288;
    const int rr = s % RGR, ch = s / RGR;   // ch in 0..2
    const int rm = rr ? rr-1 : 0, rp = (rr < RGR-1) ? rr+1 : RGR-1;
    unsigned* rawS = smu + (m ? G0 : P0);
    unsigned* bndD = smu + (m ? G1 : P1);
    unsigned* myC  = smu + CBASE + m*CSZ;
    unsigned* otC  = smu + CBASE + (1-m)*CSZ;
    const bool rowin  = ((unsigned)(oy+rr)) < (unsigned)IMG;
    const bool rowown = (rr >= HALO) & (rr < HALO+OT) & ((oy+rr) < IMG);
    const int msel = (txi == TPD-1) ? 1 : 0;

    // ---- boundary: maxpool3 - minpool3 (fused 2D), -inf at out-of-image px
    {
        bool colEdge = (txi == 0) | (txi == TPD-1);
        const int rs[3] = {rm, rr, rp};
#pragma unroll
        for (int sc = 0; sc < 2; sc++) {
            int wb = ch*16 + sc*8;
            unsigned vx[10], vn[10];
#pragma unroll
            for (int q = 0; q < 3; q++) {
                int bq = rs[q]*RSTRW + wb;
                uint4 A = *(const uint4*)(rawS+bq), Bv = *(const uint4*)(rawS+bq+4);
                unsigned em = wb ? rawS[bq-1] : A.x;
                unsigned ep = (wb+8 < ROWW) ? rawS[bq+8] : Bv.w;
                unsigned row[10] = {em,A.x,A.y,A.z,A.w,Bv.x,Bv.y,Bv.z,Bv.w,ep};
#pragma unroll
                for (int i = 0; i < 10; i++) {
                    if (q == 0) { vx[i] = row[i]; vn[i] = row[i]; }
                    else { vx[i] = hmax2u(vx[i],row[i]); vn[i] = hmin2u(vn[i],row[i]); }
                }
            }
            unsigned o[8];
#pragma unroll
            for (int i = 0; i < 8; i++) {
                unsigned hx = max3w(vx[i+1], SHW(vx[i],vx[i+1]), SHW(vx[i+1],vx[i+2]));
                unsigned hn = hmin2u(vn[i+1], hmin2u(SHW(vn[i],vn[i+1]), SHW(vn[i+1],vn[i+2])));
                __half2 bh = __hsub2(*(__half2*)&hx, *(__half2*)&hn);
                unsigned bnd = *(unsigned*)&bh;
                if (colEdge) {
                    int p0 = ox + 2*(wb+i);
                    unsigned keep = (((unsigned)p0 < IMG) ? 0x0000FFFFu : 0u)
                                  | (((unsigned)(p0+1) < IMG) ? 0xFFFF0000u : 0u);
                    bnd = (bnd & keep) | (NEGU & ~keep);
                }
                o[i] = rowin ? bnd : NEGU;
            }
            int base = rr*RSTRW + wb;
            *(uint4*)(bndD+base)   = make_uint4(o[0],o[1],o[2],o[3]);
            *(uint4*)(bndD+base+4) = make_uint4(o[4],o[5],o[6],o[7]);
            if ((rr >= HALO) & (rr < HALO+OT)) {
                int cb = (rr-HALO)*RSTRW + wb;
                *(uint4*)(myC+cb)   = make_uint4(o[0],o[1],o[2],o[3]);
                *(uint4*)(myC+cb+4) = make_uint4(o[4],o[5],o[6],o[7]);
            }
        }
    }
    __syncthreads();

    // ---- fused-2D dilation cascade d = 1..10 (ping-pong bndD <-> rawS, 1 sync/step)
    {
        unsigned* cur = bndD;
        unsigned* nxt = rawS;
        const int rs[3] = {rm, rr, rp};
        for (int d = 1; d <= 10; d++) {
            float sd = 0.f;
#pragma unroll
            for (int sc = 0; sc < 2; sc++) {
                int wb = ch*16 + sc*8;
                unsigned vx[10];
#pragma unroll
                for (int q = 0; q < 3; q++) {
                    int bq = rs[q]*RSTRW + wb;
                    uint4 A = *(const uint4*)(cur+bq), Bv = *(const uint4*)(cur+bq+4);
                    unsigned em = wb ? cur[bq-1] : A.x;
                    unsigned ep = (wb+8 < ROWW) ? cur[bq+8] : Bv.w;
                    unsigned row[10] = {em,A.x,A.y,A.z,A.w,Bv.x,Bv.y,Bv.z,Bv.w,ep};
#pragma unroll
                    for (int i = 0; i < 10; i++)
                        vx[i] = q ? hmax2u(vx[i], row[i]) : row[i];
                }
                unsigned o[8];
#pragma unroll
                for (int i = 0; i < 8; i++)
                    o[i] = max3w(vx[i+1], SHW(vx[i],vx[i+1]), SHW(vx[i+1],vx[i+2]));
                int base = rr*RSTRW + wb;
                *(uint4*)(nxt+base)   = make_uint4(o[0],o[1],o[2],o[3]);
                *(uint4*)(nxt+base+4) = make_uint4(o[4],o[5],o[6],o[7]);
                if (rowown) {
                    int cb = (rr-HALO)*RSTRW + wb;
                    uint4 C1 = *(const uint4*)(otC+cb), C2 = *(const uint4*)(otC+cb+4);
                    unsigned cw[8] = {C1.x,C1.y,C1.z,C1.w,C2.x,C2.y,C2.z,C2.w};
                    unsigned acc = 0u;
#pragma unroll
                    for (int i = 0; i < 8; i++)
                        acc = hadd2u(acc, habsdiff2u(o[i],cw[i]) & ACCM[msel][ch][sc][i]);
                    float2 f = __half22float2(*(__half2*)&acc);
                    sd += f.x + f.y;
                }
            }
            a_hd += (0.1f*(float)d) * sd;
            __syncthreads();
            unsigned* t = cur; cur = nxt; nxt = t;
        }
    }

    // ---- block reduction -> per-tile partials
    const unsigned FULL = 0xffffffffu;
#pragma unroll
    for (int o = 16; o; o >>= 1) {
        a_bce += __shfl_down_sync(FULL,a_bce,o); a_hd += __shfl_down_sync(FULL,a_hd,o);
        a_p += __shfl_down_sync(FULL,a_p,o); a_t += __shfl_down_sync(FULL,a_t,o);
        a_pt += __shfl_down_sync(FULL,a_pt,o);
    }
    int lane = tid & 31, w = tid >> 5;
    if (lane == 0) {
        red[w] = a_bce; red[18+w] = a_hd; red[36+w] = a_p;
        red[54+w] = a_t; red[72+w] = a_pt;
    }
    __syncthreads();
    if (tid == 0) {
        float sb=0, sh=0, sp=0, st=0, spt=0;
#pragma unroll
        for (int i = 0; i < 18; i++) {
            sb += red[i]; sh += red[18+i]; sp += red[36+i];
            st += red[54+i]; spt += red[72+i];
        }
        float* g = &g_part[tile*5];
        g[0]=sb; g[1]=sh; g[2]=sp; g[3]=st; g[4]=spt;
        __threadfence();
        unsigned v = atomicAdd(&g_count, 1u);
        red[96] = (v == NTILES-1) ? 1.f : 0.f;
    }
    __syncthreads();

    // ---- last CTA: final combine
    if (red[96] != 0.f) {
        __threadfence();
        __shared__ float simg[16][2], sbh[16][2];
        for (int img = w; img < 16; img += 18) {
            float bce=0, hd=0, p=0, t=0, pt=0;
            for (int i = lane; i < TPD*TPD; i += 32) {
                const float* g = &g_part[(img*TPD*TPD+i)*5];
                bce += g[0]; hd += g[1]; p += g[2]; t += g[3]; pt += g[4];
            }
#pragma unroll
            for (int o = 16; o; o >>= 1) {
                bce += __shfl_down_sync(FULL,bce,o); hd += __shfl_down_sync(FULL,hd,o);
                p += __shfl_down_sync(FULL,p,o); t += __shfl_down_sync(FULL,t,o);
                pt += __shfl_down_sync(FULL,pt,o);
            }
            if (lane == 0) {
                float dice = (2.f*pt + 1e-6f) / (p + t + 1e-6f + 1e-7f);
                float FP = p - pt, FN = t - pt;
                float tv = (pt + 1e-6f) / (pt + 0.7f*FP + 0.3f*FN + 1e-6f + 1e-7f);
                simg[img][0] = 1.f - dice;
                simg[img][1] = powf(fmaxf(1.f - tv, 0.f), 0.75f);
                sbh[img][0] = bce; sbh[img][1] = hd;
            }
        }
        __syncthreads();
        if (tid == 0) {
            float ds=0, fs=0, sb=0, sh=0;
#pragma unroll
            for (int i = 0; i < 16; i++) {
                ds += simg[i][0]; fs += simg[i][1];
                sb += sbh[i][0];  sh += sbh[i][1];
            }
            const float N = (float)NB*IMG*IMG;
            out[0] = sb/N + ds/16.f + fs/16.f + 0.1f*((sh/N)/(5.5f + 1e-8f));
            g_count = 0;
        }
    }
}

extern "C" void kernel_launch(void* const* d_in, const int* in_sizes, int n_in,
                              void* d_out, int out_size) {
    const float* logits = (const float*)d_in[0];
    const int*   target = (const int*)d_in[1];
    cudaFuncSetAttribute(k_main, cudaFuncAttributeMaxDynamicSharedMemorySize, SMEM_BYTES);
    k_main<<<NTILES, NTHR, SMEM_BYTES>>>(logits, target, (float*)d_out);
}